// round 13
// baseline (speedup 1.0000x reference)
#include <cuda_runtime.h>

#define SQH 0.70710678118654752440f
typedef unsigned long long u64;

// ---------------- f32x2 packed helpers -------------------------------------
__device__ __forceinline__ u64 pk(float v) {
    u64 r; asm("mov.b64 %0, {%1,%1};" : "=l"(r) : "f"(v)); return r;
}
__device__ __forceinline__ u64 pk2(float a, float b) {
    u64 r; asm("mov.b64 %0, {%1,%2};" : "=l"(r) : "f"(a), "f"(b)); return r;
}
__device__ __forceinline__ u64 f2fma(u64 a, u64 b, u64 c) {
    u64 d; asm("fma.rn.f32x2 %0, %1, %2, %3;" : "=l"(d) : "l"(a), "l"(b), "l"(c));
    return d;
}

// ---------------- warp-level gates: lane l holds amplitude index l ---------
template<int P>
__device__ __forceinline__ void w_rz(int l, float& ar, float& ai, float c, float s) {
    float t = ((l >> P) & 1) ? -s : s;
    float r = ar, i = ai;
    ar = fmaf(t, i, c * r);
    ai = fmaf(-t, r, c * i);
}
template<int PA, int PB>
__device__ __forceinline__ void w_zz(int l, float& ar, float& ai, float c, float s) {
    float t = (((l >> PA) ^ (l >> PB)) & 1) ? -s : s;
    float r = ar, i = ai;
    ar = fmaf(t, i, c * r);
    ai = fmaf(-t, r, c * i);
}
// M = (RX(-90)xRX(-90)) CNOT (RX(+90)xRX(+90)) : 3 independent shuffle pairs
template<int PA, int PB>
__device__ __forceinline__ void w_mid(int l, float& ar, float& ai) {
    float xbr = __shfl_xor_sync(0xffffffffu, ar, 1 << PB);
    float xbi = __shfl_xor_sync(0xffffffffu, ai, 1 << PB);
    float xar = __shfl_xor_sync(0xffffffffu, ar, 1 << PA);
    float xai = __shfl_xor_sync(0xffffffffu, ai, 1 << PA);
    float xdr = __shfl_xor_sync(0xffffffffu, ar, (1 << PA) | (1 << PB));
    float xdi = __shfl_xor_sync(0xffffffffu, ai, (1 << PA) | (1 << PB));
    float s1r = ar + xbr, s1i = ai + xbi;
    float t1r = xdr - xar, t1i = xdi - xai;
    float sg = ((l >> PA) & 1) ? -1.0f : 1.0f;
    ar = 0.5f * fmaf(-sg, t1i, s1r);
    ai = 0.5f * fmaf(sg, t1r, s1i);
}
template<int P>
__device__ __forceinline__ void w_ry(int l, float& ar, float& ai, float c, float sn) {
    float pr = __shfl_xor_sync(0xffffffffu, ar, 1 << P);
    float pi = __shfl_xor_sync(0xffffffffu, ai, 1 << P);
    float sg = ((l >> P) & 1) ? sn : -sn;
    ar = fmaf(sg, pr, c * ar);
    ai = fmaf(sg, pi, c * ai);
}
template<int PC, int PT>
__device__ __forceinline__ void w_cnot(int l, float& ar, float& ai) {
    float pr = __shfl_xor_sync(0xffffffffu, ar, 1 << PT);
    float pi = __shfl_xor_sync(0xffffffffu, ai, 1 << PT);
    if ((l >> PC) & 1) { ar = pr; ai = pi; }
}
template<int PC, int PT>
__device__ __forceinline__ void w_cry(int l, float& ar, float& ai, float c, float sn) {
    float pr = __shfl_xor_sync(0xffffffffu, ar, 1 << PT);
    float pi = __shfl_xor_sync(0xffffffffu, ai, 1 << PT);
    if ((l >> PC) & 1) {
        float sg = ((l >> PT) & 1) ? sn : -sn;
        ar = fmaf(sg, pr, c * ar);
        ai = fmaf(sg, pi, c * ai);
    }
}
template<int PC, int PT>
__device__ __forceinline__ void w_crx(int l, float& ar, float& ai, float c, float sn) {
    float pr = __shfl_xor_sync(0xffffffffu, ar, 1 << PT);
    float pi = __shfl_xor_sync(0xffffffffu, ai, 1 << PT);
    if ((l >> PC) & 1) {
        float r = ar, i = ai;
        ar = fmaf(sn, pi, c * r);
        ai = fmaf(-sn, pr, c * i);
    }
}

// Fused conv iteration: ZZ(t1) -> M -> RZ_b(t2)  (CZ pair cancels exactly)
template<int PA, int PB>
__device__ __forceinline__ void conv_f(int l, float& ar, float& ai,
                                       float2 a1, float2 a2) {
    w_zz<PA, PB>(l, ar, ai, a1.x, a1.y);
    w_mid<PA, PB>(l, ar, ai);
    w_rz<PB>(l, ar, ai, a2.x, a2.y);
}

template<int PA, int PB>
__device__ __forceinline__ void pool_blk(int l, float& ar, float& ai,
                                         float2 a0, float2 a1) {
    float c0 = a0.x, s0 = a0.y, c1 = a1.x, s1 = a1.y;
    w_ry<PA>(l, ar, ai, c0, s0);
    w_ry<PB>(l, ar, ai, c1, s1);
    w_cnot<PA, PB>(l, ar, ai);
    w_cry<PB, PA>(l, ar, ai, c0, s0);
    w_crx<PA, PB>(l, ar, ai, c1, s1);
    w_cnot<PB, PA>(l, ar, ai);
}

// ------- mode transform (division-free): base-4 digit -> 3-basis coeff -----
__device__ __forceinline__ void mode_xform(const float2* __restrict__ In,
                                           float2* __restrict__ Out, int S) {
    for (int rest = threadIdx.x; rest < S; rest += 256) {
        float2 a = In[rest];
        float2 b = In[3 * S + rest];
        float2 c = In[S + rest];
        float2 d = In[2 * S + rest];
        Out[rest * 3 + 0] = make_float2(0.5f * (a.x + b.x), 0.5f * (a.y + b.y));
        Out[rest * 3 + 1] = make_float2(0.5f * (a.x - b.x), 0.5f * (a.y - b.y));
        Out[rest * 3 + 2] = make_float2(0.5f * (c.x + d.x), 0.5f * (c.y + d.y));
    }
}

// ---------------- eval N elements against smem T (R6-proven shape) ---------
template<int N>
__device__ __forceinline__ void eval_n(const u64* __restrict__ sT,
                                       const float xv[4][5], u64 accT[N]) {
    u64 C4[N], S4[N], C3[N], S3[N], C2[N], S2[N];
    float c1f[N], s1f[N], c0f[N], s0f[N];
#pragma unroll
    for (int e = 0; e < N; e++) {
        float cv, sv;
        __sincosf(xv[e][4], &sv, &cv); C4[e] = pk(cv); S4[e] = pk(sv);
        __sincosf(xv[e][3], &sv, &cv); C3[e] = pk(cv); S3[e] = pk(sv);
        __sincosf(xv[e][2], &sv, &cv); C2[e] = pk(cv); S2[e] = pk(sv);
        __sincosf(xv[e][1], &sv, &cv); c1f[e] = cv; s1f[e] = sv;
        __sincosf(xv[e][0], &sv, &cv); c0f[e] = cv; s0f[e] = sv;
    }
    u64 acc3[N], acc2[N];
#pragma unroll
    for (int e4 = 0; e4 < 3; e4++) {
#pragma unroll
        for (int e3 = 0; e3 < 3; e3++) {
#pragma unroll
            for (int e2 = 0; e2 < 3; e2++) {
                int r = (e4 * 3 + e3) * 3 + e2;
                const u64* row = sT + r * 10;
                ulonglong2 q0 = *(const ulonglong2*)(row + 0);  // t0 t1
                ulonglong2 q1 = *(const ulonglong2*)(row + 2);  // t2 t3
                ulonglong2 q2 = *(const ulonglong2*)(row + 4);  // t4 t5
                ulonglong2 q3 = *(const ulonglong2*)(row + 6);  // t6 t7
                u64 t8 = row[8];
#pragma unroll
                for (int e = 0; e < N; e++) {
                    u64 g0 = f2fma(S4[e], q1.x, f2fma(C4[e], q0.y, q0.x));
                    u64 g1 = f2fma(S4[e], q2.y, f2fma(C4[e], q2.x, q1.y));
                    u64 g2 = f2fma(S4[e], t8,   f2fma(C4[e], q3.y, q3.x));
                    u64 d  = f2fma(S3[e], g2,   f2fma(C3[e], g1, g0));
                    if (e2 == 0)      acc2[e] = d;
                    else if (e2 == 1) acc2[e] = f2fma(C2[e], d, acc2[e]);
                    else              acc2[e] = f2fma(S2[e], d, acc2[e]);
                }
            }
#pragma unroll
            for (int e = 0; e < N; e++) {
                if (e3 == 0)      acc3[e] = acc2[e];
                else if (e3 == 1) acc3[e] = f2fma(pk(c1f[e]), acc2[e], acc3[e]);
                else              acc3[e] = f2fma(pk(s1f[e]), acc2[e], acc3[e]);
            }
        }
#pragma unroll
        for (int e = 0; e < N; e++) {
            if (e4 == 0)      accT[e] = acc3[e];
            else if (e4 == 1) accT[e] = f2fma(pk(c0f[e]), acc3[e], accT[e]);
            else              accT[e] = f2fma(pk(s0f[e]), acc3[e], accT[e]);
        }
    }
}

// ============== single fused kernel: per-block prep + batch eval ============
// 256 threads/block, 2 blocks/SM; warps 0-3 eval 4 elems, warps 4-7 eval 3.
// Block covers 896 contiguous elements; grid = ceil(B / 896) = 293.
#define TPB 256
#define EPB 896
__global__ void __launch_bounds__(TPB, 2)
qcnn_fused(const float* __restrict__ x, const float* __restrict__ conv,
           const float* __restrict__ pool, const float* __restrict__ fcw,
           const float* __restrict__ fcb, float2* __restrict__ out, int B) {
    __shared__ float2 bufA[1088];   // U as bufA[j*33+l]; later base-4 A [1024]
    __shared__ float2 bufB[768];
    __shared__ u64 sT[272];         // class-packed T: row r at r*10, 9 used
    __shared__ float2 sAng[17];     // precomputed sincos(0.5*angle)

    int tid = threadIdx.x;
    int chunk = blockIdx.x * EPB;
    bool hi = (tid < 128);                       // warps 0-3: 4 elems
    int base = chunk + (hi ? tid : 512 + (tid - 128));
    int nloc = hi ? 4 : 3;

    // ---- prefetch x (clamped); DRAM latency hides behind prep ----
    float xv[4][5];
#pragma unroll
    for (int e = 0; e < 4; e++) {
        if (e < nloc) {
            int idx = base + e * 128;
            idx = idx < B ? idx : B - 1;        // clamp: value unused if OOB
#pragma unroll
            for (int q = 0; q < 5; q++)
                xv[e][q] = __ldg(x + idx * 5 + q);
        }
    }

    // ---- phase 0: 17 angle sincos, once per block ----
    if (tid < 17) {
        float a;
        if (tid < 7)       a = conv[tid];           // layer0 conv[0..6]
        else if (tid < 13) a = conv[15 + tid - 7];  // layer1 conv[15..20]
        else               a = pool[tid - 13];      // pool[0..3]
        float cc, ss;
        sincosf(0.5f * a, &ss, &cc);
        sAng[tid] = make_float2(cc, ss);
    }
    __syncthreads();

    // ---- phase 1: simulate U; 8 warps x 4 columns, lane = amplitude ----
    {
        int w = tid >> 5;
        int l = tid & 31;
#pragma unroll
        for (int half = 0; half < 4; half++) {
            int j = w + half * 8;
            float ar = (l == j) ? 1.0f : 0.0f, ai = 0.0f;
            // Layer 0: wires [0..4], pos(w) = 4 - w
            conv_f<4, 3>(l, ar, ai, sAng[0], sAng[2]);
            conv_f<3, 2>(l, ar, ai, sAng[1], sAng[3]);
            conv_f<2, 1>(l, ar, ai, sAng[2], sAng[4]);
            conv_f<1, 0>(l, ar, ai, sAng[3], sAng[5]);
            conv_f<0, 4>(l, ar, ai, sAng[4], sAng[6]);
            pool_blk<4, 3>(l, ar, ai, sAng[13], sAng[14]);
            // Layer 1: wires [1..4]
            conv_f<3, 2>(l, ar, ai, sAng[7], sAng[9]);
            conv_f<2, 1>(l, ar, ai, sAng[8], sAng[10]);
            conv_f<1, 0>(l, ar, ai, sAng[9], sAng[11]);
            conv_f<0, 3>(l, ar, ai, sAng[10], sAng[12]);
            pool_blk<3, 2>(l, ar, ai, sAng[15], sAng[16]);
            bufA[j * 33 + l] = make_float2(ar, ai);   // U[l][j]
        }
    }
    __syncthreads();

    // ---- phase 2: A_c[s][t] folded with fc_w, scatter base-4 (4/thread) ----
    {
        float r0[4], r1[4];
        int dd[4];
#pragma unroll
        for (int it = 0; it < 4; it++) {
            int idx = tid + it * 256;
            int s = idx >> 5, t = idx & 31;
            float m2 = 0.0f, m3 = 0.0f;
#pragma unroll
            for (int k = 0; k < 32; k++) {
                float2 us = bufA[s * 33 + k];
                float2 ut = bufA[t * 33 + k];
                float pr = us.x * ut.x + us.y * ut.y;
                m2 += ((k >> 2) & 1) ? -pr : pr;   // measured wire 2 (bit 2)
                m3 += ((k >> 1) & 1) ? -pr : pr;   // measured wire 3 (bit 1)
            }
            r0[it] = fcw[0] * m2 + fcw[1] * m3;
            r1[it] = fcw[2] * m2 + fcw[3] * m3;
            int d = 0;
#pragma unroll
            for (int P = 0; P < 5; P++)
                d += ((((s >> P) & 1) * 2 + ((t >> P) & 1)) << (2 * P));
            dd[it] = d;
        }
        __syncthreads();
#pragma unroll
        for (int it = 0; it < 4; it++)
            bufA[dd[it]] = make_float2(r0[it], r1[it]);
    }
    __syncthreads();

    // ---- phase 3: 5 mode transforms 1024 -> 243 (division-free) ----
    mode_xform(bufA, bufB, 256); __syncthreads();
    mode_xform(bufB, bufA, 192); __syncthreads();
    mode_xform(bufA, bufB, 144); __syncthreads();
    mode_xform(bufB, bufA, 108); __syncthreads();
    mode_xform(bufA, bufB, 81);  __syncthreads();

    // ---- phase 4: class-packed T rows (stride 10 u64); fold bias into T[0]
    if (tid < 243) {
        float2 v = bufB[tid];
        if (tid == 0) { v.x += fcb[0]; v.y += fcb[1]; }
        sT[(tid / 9) * 10 + (tid % 9)] = pk2(v.x, v.y);
    }
    __syncthreads();

    // ---- phase 5: eval; warps 0-3 do 4 elements, warps 4-7 do 3 ----
    u64* o = (u64*)out;
    if (hi) {
        u64 accT[4];
        eval_n<4>(sT, xv, accT);
#pragma unroll
        for (int e = 0; e < 4; e++) {
            int idx = base + e * 128;
            if (idx < B) o[idx] = accT[e];
        }
    } else {
        u64 accT[3];
        eval_n<3>(sT, xv, accT);
#pragma unroll
        for (int e = 0; e < 3; e++) {
            int idx = base + e * 128;
            if (idx < B) o[idx] = accT[e];
        }
    }
}

extern "C" void kernel_launch(void* const* d_in, const int* in_sizes, int n_in,
                              void* d_out, int out_size) {
    const float* x    = (const float*)d_in[0];  // (B, 5)
    const float* conv = (const float*)d_in[1];  // (2, 15)
    const float* pool = (const float*)d_in[2];  // (2, 2)
    const float* fcw  = (const float*)d_in[3];  // (2, 2)
    const float* fcb  = (const float*)d_in[4];  // (2,)
    float2* out = (float2*)d_out;

    int B = in_sizes[0] / 5;
    int blocks = (B + EPB - 1) / EPB;      // 293 @ B=262144, 2 blocks/SM
    qcnn_fused<<<blocks, TPB>>>(x, conv, pool, fcw, fcb, out, B);
}

// round 14
// speedup vs baseline: 1.2925x; 1.2925x over previous
#include <cuda_runtime.h>

#define SQH 0.70710678118654752440f
typedef unsigned long long u64;

// ---------------- f32x2 packed helpers -------------------------------------
__device__ __forceinline__ u64 pk(float v) {
    u64 r; asm("mov.b64 %0, {%1,%1};" : "=l"(r) : "f"(v)); return r;
}
__device__ __forceinline__ u64 pk2(float a, float b) {
    u64 r; asm("mov.b64 %0, {%1,%2};" : "=l"(r) : "f"(a), "f"(b)); return r;
}
__device__ __forceinline__ u64 f2fma(u64 a, u64 b, u64 c) {
    u64 d; asm("fma.rn.f32x2 %0, %1, %2, %3;" : "=l"(d) : "l"(a), "l"(b), "l"(c));
    return d;
}

// ---------------- warp-level gates: lane l holds amplitude index l ---------
template<int P>
__device__ __forceinline__ void w_rz(int l, float& ar, float& ai, float c, float s) {
    float t = ((l >> P) & 1) ? -s : s;
    float r = ar, i = ai;
    ar = fmaf(t, i, c * r);
    ai = fmaf(-t, r, c * i);
}
template<int PA, int PB>
__device__ __forceinline__ void w_zz(int l, float& ar, float& ai, float c, float s) {
    float t = (((l >> PA) ^ (l >> PB)) & 1) ? -s : s;
    float r = ar, i = ai;
    ar = fmaf(t, i, c * r);
    ai = fmaf(-t, r, c * i);
}
// M = (RX(-90)xRX(-90)) CNOT (RX(+90)xRX(+90)) : 3 independent shuffle pairs
template<int PA, int PB>
__device__ __forceinline__ void w_mid(int l, float& ar, float& ai) {
    float xbr = __shfl_xor_sync(0xffffffffu, ar, 1 << PB);
    float xbi = __shfl_xor_sync(0xffffffffu, ai, 1 << PB);
    float xar = __shfl_xor_sync(0xffffffffu, ar, 1 << PA);
    float xai = __shfl_xor_sync(0xffffffffu, ai, 1 << PA);
    float xdr = __shfl_xor_sync(0xffffffffu, ar, (1 << PA) | (1 << PB));
    float xdi = __shfl_xor_sync(0xffffffffu, ai, (1 << PA) | (1 << PB));
    float s1r = ar + xbr, s1i = ai + xbi;
    float t1r = xdr - xar, t1i = xdi - xai;
    float sg = ((l >> PA) & 1) ? -1.0f : 1.0f;
    ar = 0.5f * fmaf(-sg, t1i, s1r);
    ai = 0.5f * fmaf(sg, t1r, s1i);
}
template<int P>
__device__ __forceinline__ void w_ry(int l, float& ar, float& ai, float c, float sn) {
    float pr = __shfl_xor_sync(0xffffffffu, ar, 1 << P);
    float pi = __shfl_xor_sync(0xffffffffu, ai, 1 << P);
    float sg = ((l >> P) & 1) ? sn : -sn;
    ar = fmaf(sg, pr, c * ar);
    ai = fmaf(sg, pi, c * ai);
}
template<int PC, int PT>
__device__ __forceinline__ void w_cnot(int l, float& ar, float& ai) {
    float pr = __shfl_xor_sync(0xffffffffu, ar, 1 << PT);
    float pi = __shfl_xor_sync(0xffffffffu, ai, 1 << PT);
    if ((l >> PC) & 1) { ar = pr; ai = pi; }
}
template<int PC, int PT>
__device__ __forceinline__ void w_cry(int l, float& ar, float& ai, float c, float sn) {
    float pr = __shfl_xor_sync(0xffffffffu, ar, 1 << PT);
    float pi = __shfl_xor_sync(0xffffffffu, ai, 1 << PT);
    if ((l >> PC) & 1) {
        float sg = ((l >> PT) & 1) ? sn : -sn;
        ar = fmaf(sg, pr, c * ar);
        ai = fmaf(sg, pi, c * ai);
    }
}
template<int PC, int PT>
__device__ __forceinline__ void w_crx(int l, float& ar, float& ai, float c, float sn) {
    float pr = __shfl_xor_sync(0xffffffffu, ar, 1 << PT);
    float pi = __shfl_xor_sync(0xffffffffu, ai, 1 << PT);
    if ((l >> PC) & 1) {
        float r = ar, i = ai;
        ar = fmaf(sn, pi, c * r);
        ai = fmaf(-sn, pr, c * i);
    }
}

// Fused conv iteration: ZZ(t1) -> M -> RZ_b(t2)  (CZ pair cancels exactly)
template<int PA, int PB>
__device__ __forceinline__ void conv_f(int l, float& ar, float& ai,
                                       float2 a1, float2 a2) {
    w_zz<PA, PB>(l, ar, ai, a1.x, a1.y);
    w_mid<PA, PB>(l, ar, ai);
    w_rz<PB>(l, ar, ai, a2.x, a2.y);
}

template<int PA, int PB>
__device__ __forceinline__ void pool_blk(int l, float& ar, float& ai,
                                         float2 a0, float2 a1) {
    float c0 = a0.x, s0 = a0.y, c1 = a1.x, s1 = a1.y;
    w_ry<PA>(l, ar, ai, c0, s0);
    w_ry<PB>(l, ar, ai, c1, s1);
    w_cnot<PA, PB>(l, ar, ai);
    w_cry<PB, PA>(l, ar, ai, c0, s0);
    w_crx<PA, PB>(l, ar, ai, c1, s1);
    w_cnot<PB, PA>(l, ar, ai);
}

// ------- mode transform (division-free): base-4 digit -> 3-basis coeff -----
__device__ __forceinline__ void mode_xform(const float2* __restrict__ In,
                                           float2* __restrict__ Out, int S) {
    for (int rest = threadIdx.x; rest < S; rest += 512) {
        float2 a = In[rest];
        float2 b = In[3 * S + rest];
        float2 c = In[S + rest];
        float2 d = In[2 * S + rest];
        Out[rest * 3 + 0] = make_float2(0.5f * (a.x + b.x), 0.5f * (a.y + b.y));
        Out[rest * 3 + 1] = make_float2(0.5f * (a.x - b.x), 0.5f * (a.y - b.y));
        Out[rest * 3 + 2] = make_float2(0.5f * (c.x + d.x), 0.5f * (c.y + d.y));
    }
}

// ----- eval N elements against smem T, software-pipelined row loads --------
template<int N>
__device__ __forceinline__ void eval_n(const u64* __restrict__ sT,
                                       const float xv[4][5], u64 accT[N]) {
    u64 C4[N], S4[N], C3[N], S3[N], C2[N], S2[N];
    float c1f[N], s1f[N], c0f[N], s0f[N];
#pragma unroll
    for (int e = 0; e < N; e++) {
        float cv, sv;
        __sincosf(xv[e][4], &sv, &cv); C4[e] = pk(cv); S4[e] = pk(sv);
        __sincosf(xv[e][3], &sv, &cv); C3[e] = pk(cv); S3[e] = pk(sv);
        __sincosf(xv[e][2], &sv, &cv); C2[e] = pk(cv); S2[e] = pk(sv);
        __sincosf(xv[e][1], &sv, &cv); c1f[e] = cv; s1f[e] = sv;
        __sincosf(xv[e][0], &sv, &cv); c0f[e] = cv; s0f[e] = sv;
    }
    u64 acc3[N], acc2[N];

    // prime row 0
    ulonglong2 ca0 = *(const ulonglong2*)(sT + 0);
    ulonglong2 ca1 = *(const ulonglong2*)(sT + 2);
    ulonglong2 ca2 = *(const ulonglong2*)(sT + 4);
    ulonglong2 ca3 = *(const ulonglong2*)(sT + 6);
    u64 ca8 = sT[8];

#pragma unroll
    for (int r = 0; r < 27; r++) {
        int e2 = r % 3, e3 = (r / 3) % 3, e4 = r / 9;
        // issue next row's loads BEFORE this row's FMA block
        ulonglong2 nb0, nb1, nb2, nb3; u64 nb8;
        if (r < 26) {
            const u64* nr = sT + (r + 1) * 10;
            nb0 = *(const ulonglong2*)(nr + 0);
            nb1 = *(const ulonglong2*)(nr + 2);
            nb2 = *(const ulonglong2*)(nr + 4);
            nb3 = *(const ulonglong2*)(nr + 6);
            nb8 = nr[8];
        }
#pragma unroll
        for (int e = 0; e < N; e++) {
            u64 g0 = f2fma(S4[e], ca1.x, f2fma(C4[e], ca0.y, ca0.x));
            u64 g1 = f2fma(S4[e], ca2.y, f2fma(C4[e], ca2.x, ca1.y));
            u64 g2 = f2fma(S4[e], ca8,   f2fma(C4[e], ca3.y, ca3.x));
            u64 d  = f2fma(S3[e], g2,    f2fma(C3[e], g1, g0));
            if (e2 == 0)      acc2[e] = d;
            else if (e2 == 1) acc2[e] = f2fma(C2[e], d, acc2[e]);
            else              acc2[e] = f2fma(S2[e], d, acc2[e]);
        }
        if (e2 == 2) {
#pragma unroll
            for (int e = 0; e < N; e++) {
                if (e3 == 0)      acc3[e] = acc2[e];
                else if (e3 == 1) acc3[e] = f2fma(pk(c1f[e]), acc2[e], acc3[e]);
                else              acc3[e] = f2fma(pk(s1f[e]), acc2[e], acc3[e]);
            }
            if (e3 == 2) {
#pragma unroll
                for (int e = 0; e < N; e++) {
                    if (e4 == 0)      accT[e] = acc3[e];
                    else if (e4 == 1) accT[e] = f2fma(pk(c0f[e]), acc3[e], accT[e]);
                    else              accT[e] = f2fma(pk(s0f[e]), acc3[e], accT[e]);
                }
            }
        }
        ca0 = nb0; ca1 = nb1; ca2 = nb2; ca3 = nb3; ca8 = nb8;
    }
}

// ============== single fused kernel: per-block prep + batch eval ============
// 512 threads/block; warps 0-7 eval 4 elements, warps 8-15 eval 3.
// Block covers 1792 contiguous elements; grid = ceil(B / 1792) = 147.
#define TPB 512
#define EPB 1792
__global__ void __launch_bounds__(TPB, 1)
qcnn_fused(const float* __restrict__ x, const float* __restrict__ conv,
           const float* __restrict__ pool, const float* __restrict__ fcw,
           const float* __restrict__ fcb, float2* __restrict__ out, int B) {
    __shared__ float2 bufA[1088];   // U as bufA[j*33+l]; later base-4 A [1024]
    __shared__ float2 bufB[768];
    __shared__ u64 sT[272];         // class-packed T: row r at r*10, 9 used
    __shared__ float2 sAng[17];     // precomputed sincos(0.5*angle)

    int tid = threadIdx.x;
    int chunk = blockIdx.x * EPB;
    bool hi = (tid < 256);                       // warps 0-7: 4 elems
    int base = chunk + (hi ? tid : 1024 + (tid - 256));
    int nloc = hi ? 4 : 3;

    // ---- prefetch x (clamped); DRAM latency hides behind prep ----
    float xv[4][5];
#pragma unroll
    for (int e = 0; e < 4; e++) {
        if (e < nloc) {
            int idx = base + e * 256;
            idx = idx < B ? idx : B - 1;        // clamp: value unused if OOB
#pragma unroll
            for (int q = 0; q < 5; q++)
                xv[e][q] = __ldg(x + idx * 5 + q);
        }
    }

    // ---- phase 0: 17 angle sincos, once per block ----
    if (tid < 17) {
        float a;
        if (tid < 7)       a = conv[tid];           // layer0 conv[0..6]
        else if (tid < 13) a = conv[15 + tid - 7];  // layer1 conv[15..20]
        else               a = pool[tid - 13];      // pool[0..3]
        float cc, ss;
        sincosf(0.5f * a, &ss, &cc);
        sAng[tid] = make_float2(cc, ss);
    }
    __syncthreads();

    // ---- phase 1: simulate U; 16 warps x 2 columns, lane = amplitude ----
    {
        int w = tid >> 5;
        int l = tid & 31;
#pragma unroll
        for (int half = 0; half < 2; half++) {
            int j = w + half * 16;
            float ar = (l == j) ? 1.0f : 0.0f, ai = 0.0f;
            // Layer 0: wires [0..4], pos(w) = 4 - w
            conv_f<4, 3>(l, ar, ai, sAng[0], sAng[2]);
            conv_f<3, 2>(l, ar, ai, sAng[1], sAng[3]);
            conv_f<2, 1>(l, ar, ai, sAng[2], sAng[4]);
            conv_f<1, 0>(l, ar, ai, sAng[3], sAng[5]);
            conv_f<0, 4>(l, ar, ai, sAng[4], sAng[6]);
            pool_blk<4, 3>(l, ar, ai, sAng[13], sAng[14]);
            // Layer 1: wires [1..4]
            conv_f<3, 2>(l, ar, ai, sAng[7], sAng[9]);
            conv_f<2, 1>(l, ar, ai, sAng[8], sAng[10]);
            conv_f<1, 0>(l, ar, ai, sAng[9], sAng[11]);
            conv_f<0, 3>(l, ar, ai, sAng[10], sAng[12]);
            pool_blk<3, 2>(l, ar, ai, sAng[15], sAng[16]);
            bufA[j * 33 + l] = make_float2(ar, ai);   // U[l][j]
        }
    }
    __syncthreads();

    // ---- phase 2: A_c[s][t] folded with fc_w, scatter base-4 (2/thread) ----
    {
        float r0[2], r1[2];
        int dd[2];
#pragma unroll
        for (int it = 0; it < 2; it++) {
            int idx = tid + it * 512;
            int s = idx >> 5, t = idx & 31;
            float m2 = 0.0f, m3 = 0.0f;
#pragma unroll
            for (int k = 0; k < 32; k++) {
                float2 us = bufA[s * 33 + k];
                float2 ut = bufA[t * 33 + k];
                float pr = us.x * ut.x + us.y * ut.y;
                m2 += ((k >> 2) & 1) ? -pr : pr;   // measured wire 2 (bit 2)
                m3 += ((k >> 1) & 1) ? -pr : pr;   // measured wire 3 (bit 1)
            }
            r0[it] = fcw[0] * m2 + fcw[1] * m3;
            r1[it] = fcw[2] * m2 + fcw[3] * m3;
            int d = 0;
#pragma unroll
            for (int P = 0; P < 5; P++)
                d += ((((s >> P) & 1) * 2 + ((t >> P) & 1)) << (2 * P));
            dd[it] = d;
        }
        __syncthreads();
#pragma unroll
        for (int it = 0; it < 2; it++)
            bufA[dd[it]] = make_float2(r0[it], r1[it]);
    }
    __syncthreads();

    // ---- phase 3: 5 mode transforms 1024 -> 243 (division-free) ----
    mode_xform(bufA, bufB, 256); __syncthreads();
    mode_xform(bufB, bufA, 192); __syncthreads();
    mode_xform(bufA, bufB, 144); __syncthreads();
    mode_xform(bufB, bufA, 108); __syncthreads();
    mode_xform(bufA, bufB, 81);  __syncthreads();

    // ---- phase 4: class-packed T rows (stride 10 u64); fold bias into T[0]
    if (tid < 243) {
        float2 v = bufB[tid];
        if (tid == 0) { v.x += fcb[0]; v.y += fcb[1]; }
        sT[(tid / 9) * 10 + (tid % 9)] = pk2(v.x, v.y);
    }
    __syncthreads();

    // ---- phase 5: eval; warps 0-7 do 4 elements, warps 8-15 do 3 ----
    u64* o = (u64*)out;
    if (hi) {
        u64 accT[4];
        eval_n<4>(sT, xv, accT);
#pragma unroll
        for (int e = 0; e < 4; e++) {
            int idx = base + e * 256;
            if (idx < B) o[idx] = accT[e];
        }
    } else {
        u64 accT[3];
        eval_n<3>(sT, xv, accT);
#pragma unroll
        for (int e = 0; e < 3; e++) {
            int idx = base + e * 256;
            if (idx < B) o[idx] = accT[e];
        }
    }
}

extern "C" void kernel_launch(void* const* d_in, const int* in_sizes, int n_in,
                              void* d_out, int out_size) {
    const float* x    = (const float*)d_in[0];  // (B, 5)
    const float* conv = (const float*)d_in[1];  // (2, 15)
    const float* pool = (const float*)d_in[2];  // (2, 2)
    const float* fcw  = (const float*)d_in[3];  // (2, 2)
    const float* fcb  = (const float*)d_in[4];  // (2,)
    float2* out = (float2*)d_out;

    int B = in_sizes[0] / 5;
    int blocks = (B + EPB - 1) / EPB;      // 147 @ B=262144, one wave
    qcnn_fused<<<blocks, TPB>>>(x, conv, pool, fcw, fcb, out, B);
}